// round 3
// baseline (speedup 1.0000x reference)
#include <cuda_runtime.h>
#include <cuda_bf16.h>

#define MAP_W   64
#define MAP_H   64
#define T_SIZE  64
#define NUM_CP  8
#define BATCH   128
#define NTILES  (BATCH * (MAP_W / 4))   // 2048 tiles of (b, 4 x-columns)

// Binomial coefficients C(m, k)
__device__ const float BINOM[8][8] = {
    {1, 0, 0,  0,  0,  0,  0, 0},
    {1, 1, 0,  0,  0,  0,  0, 0},
    {1, 2, 1,  0,  0,  0,  0, 0},
    {1, 3, 3,  1,  0,  0,  0, 0},
    {1, 4, 6,  4,  1,  0,  0, 0},
    {1, 5, 10, 10, 5,  1,  0, 0},
    {1, 6, 15, 20, 15, 6,  1, 0},
    {1, 7, 21, 35, 35, 21, 7, 1},
};

__device__ __forceinline__ float ex2(float x) {
    float y;
    asm("ex2.approx.ftz.f32 %0, %1;" : "=f"(y) : "f"(x));
    return y;
}

// Persistent kernel: 592 resident blocks grid-stride over 2048 tiles.
// Block tile = (b, 4 x-columns). 256 threads = 16 t-quads x 16 y-groups.
// Each thread per tile: 4 consecutive t (float4 store), 4 x, 4 y -> 64 outputs.
__global__ __launch_bounds__(256, 4)
void probmap_kernel(const float* __restrict__ cp_means,
                    const int*   __restrict__ num_cps,
                    const float* __restrict__ cp_cov,
                    float*       __restrict__ out)
{
    __shared__ float sco[6][64];   // per-t coeffs: mx, my, Af, Bf, Cf, lscale

    const int tid = threadIdx.x;
    const int tq  = tid & 15;      // t-quad: t = 4*tq .. 4*tq+3
    const int yg  = tid >> 4;      // y-group 0..15; y = yg + 16*yi

    for (int tile = blockIdx.x; tile < NTILES; tile += gridDim.x) {
        const int b  = tile >> 4;
        const int x0 = (tile & 15) << 2;

        // ---- Cooperative per-t coefficient setup (one thread per t) ----
        __syncthreads();   // previous tile's sco reads complete
        if (tid < 64) {
            const int   t  = tid;
            const int   m  = num_cps[b] - 1;          // degree 2..7
            const float tt = (float)t * (1.0f / 63.0f);
            const float u  = 1.0f - tt;

            float up[NUM_CP];
            up[0] = 1.0f;
            #pragma unroll
            for (int j = 1; j < NUM_CP; j++) up[j] = up[j - 1] * u;

            float w[NUM_CP];
            float tk = 1.0f;
            #pragma unroll
            for (int k = 0; k < NUM_CP; k++) {
                w[k] = (k <= m) ? BINOM[m][k] * tk * up[m - k] : 0.0f;
                tk *= tt;
            }

            float mx = 0.f, my = 0.f, ca = 0.f, cb = 0.f, cd = 0.f;
            #pragma unroll
            for (int k = 0; k < NUM_CP; k++) {
                const float wk = w[k];
                const float w2 = wk * wk;
                const float* mp = cp_means + ((size_t)k * BATCH + b) * 2;
                const float* cp = cp_cov   + ((size_t)k * BATCH + b) * 4;
                mx += wk * __ldg(mp + 0);
                my += wk * __ldg(mp + 1);
                ca += w2 * __ldg(cp + 0);
                cb += w2 * __ldg(cp + 1);
                cd += w2 * __ldg(cp + 3);
            }

            const float det  = ca * cd - cb * cb;
            const float rdet = 1.0f / det;
            const float NL2E = -0.72134752044448170f;     // -0.5 * log2(e)
            sco[0][t] = mx;
            sco[1][t] = my;
            sco[2][t] = NL2E * cd * rdet;                 // Af  (dx^2)
            sco[3][t] = -2.0f * NL2E * cb * rdet;         // Bf  (dx*dy)
            sco[4][t] = NL2E * ca * rdet;                 // Cf  (dy^2)
            sco[5][t] = -0.5f * __log2f(39.478417604357434f * det); // folded norm
        }
        __syncthreads();

        // ---- Main evaluation ----
        const float4 MX = ((const float4*)sco[0])[tq];
        const float4 MY = ((const float4*)sco[1])[tq];
        const float4 AF = ((const float4*)sco[2])[tq];
        const float4 BF = ((const float4*)sco[3])[tq];
        const float4 CF = ((const float4*)sco[4])[tq];
        const float4 LS = ((const float4*)sco[5])[tq];

        const float mx[4] = {MX.x, MX.y, MX.z, MX.w};
        const float my[4] = {MY.x, MY.y, MY.z, MY.w};
        const float Af[4] = {AF.x, AF.y, AF.z, AF.w};
        const float Bf[4] = {BF.x, BF.y, BF.z, BF.w};
        const float Cf[4] = {CF.x, CF.y, CF.z, CF.w};
        const float ls[4] = {LS.x, LS.y, LS.z, LS.w};

        float ym[4];
        #pragma unroll
        for (int j = 0; j < 4; j++) ym[j] = (float)yg - my[j];

        float* ob = out + (((size_t)b * MAP_W + x0) * MAP_H) * T_SIZE + (tq << 2);

        #pragma unroll
        for (int xi = 0; xi < 4; xi++) {
            const float xf = (float)(x0 + xi);
            float A2[4], Bd[4];
            #pragma unroll
            for (int j = 0; j < 4; j++) {
                const float dx = xf - mx[j];
                A2[j] = fmaf(Af[j] * dx, dx, ls[j]);   // Af*dx^2 + log2-scale
                Bd[j] = Bf[j] * dx;
            }

            float dy0 = ym[0], dy1 = ym[1], dy2 = ym[2], dy3 = ym[3];
            float* orow = ob + (size_t)xi * MAP_H * T_SIZE + (size_t)yg * T_SIZE;

            #pragma unroll
            for (int yi = 0; yi < 4; yi++) {
                float4 v;
                v.x = ex2(fmaf(fmaf(Cf[0], dy0, Bd[0]), dy0, A2[0]));
                v.y = ex2(fmaf(fmaf(Cf[1], dy1, Bd[1]), dy1, A2[1]));
                v.z = ex2(fmaf(fmaf(Cf[2], dy2, Bd[2]), dy2, A2[2]));
                v.w = ex2(fmaf(fmaf(Cf[3], dy3, Bd[3]), dy3, A2[3]));
                __stcs((float4*)(orow + (size_t)yi * 16 * T_SIZE), v);
                dy0 += 16.0f; dy1 += 16.0f; dy2 += 16.0f; dy3 += 16.0f;
            }
        }
    }
}

extern "C" void kernel_launch(void* const* d_in, const int* in_sizes, int n_in,
                              void* d_out, int out_size)
{
    const float* cp_means = (const float*)d_in[0];   // (8, 128, 2)
    const int*   num_cps  = (const int*)  d_in[1];   // (128,)
    const float* cp_cov   = (const float*)d_in[2];   // (8, 128, 2, 2)
    float* out = (float*)d_out;                      // (128, 64, 64, 64)

    dim3 grid(148 * 4);   // persistent: one wave, grid-stride over tiles
    dim3 block(256);
    probmap_kernel<<<grid, block>>>(cp_means, num_cps, cp_cov, out);
}

// round 5
// speedup vs baseline: 1.4766x; 1.4766x over previous
#include <cuda_runtime.h>
#include <cuda_bf16.h>

#define MAP_W   64
#define MAP_H   64
#define T_SIZE  64
#define NUM_CP  8
#define BATCH   128

// Binomial coefficients C(m, k)
__device__ const float BINOM[8][8] = {
    {1, 0, 0,  0,  0,  0,  0, 0},
    {1, 1, 0,  0,  0,  0,  0, 0},
    {1, 2, 1,  0,  0,  0,  0, 0},
    {1, 3, 3,  1,  0,  0,  0, 0},
    {1, 4, 6,  4,  1,  0,  0, 0},
    {1, 5, 10, 10, 5,  1,  0, 0},
    {1, 6, 15, 20, 15, 6,  1, 0},
    {1, 7, 21, 35, 35, 21, 7, 1},
};

__device__ __forceinline__ float ex2(float x) {
    float y;
    asm("ex2.approx.ftz.f32 %0, %1;" : "=f"(y) : "f"(x));
    return y;
}

// Block = (b, 4 x-columns). 256 threads = 16 t-quads x 16 y-groups.
// Each thread: 4 consecutive t (float4 store), 4 x, 4 y -> 64 outputs.
// Grid: BATCH * (MAP_W/4) = 2048 independent blocks (max store MLP chip-wide).
__global__ __launch_bounds__(256, 5)
void probmap_kernel(const float* __restrict__ cp_means,
                    const int*   __restrict__ num_cps,
                    const float* __restrict__ cp_cov,
                    float*       __restrict__ out)
{
    __shared__ float sco[6][64];   // per-t coeffs: mx, my, Af, Bf, Cf, lscale

    const int b   = blockIdx.x >> 4;
    const int x0  = (blockIdx.x & 15) << 2;
    const int tid = threadIdx.x;

    // ---- Cooperative per-t coefficient setup (one thread per t) ----
    if (tid < 64) {
        const int   t  = tid;
        const int   m  = num_cps[b] - 1;          // degree 2..7
        const float tt = (float)t * (1.0f / 63.0f);
        const float u  = 1.0f - tt;

        float up[NUM_CP];
        up[0] = 1.0f;
        #pragma unroll
        for (int j = 1; j < NUM_CP; j++) up[j] = up[j - 1] * u;

        float w[NUM_CP];
        float tk = 1.0f;
        #pragma unroll
        for (int k = 0; k < NUM_CP; k++) {
            w[k] = (k <= m) ? BINOM[m][k] * tk * up[m - k] : 0.0f;
            tk *= tt;
        }

        float mx = 0.f, my = 0.f, ca = 0.f, cb = 0.f, cd = 0.f;
        #pragma unroll
        for (int k = 0; k < NUM_CP; k++) {
            const float wk = w[k];
            const float w2 = wk * wk;
            const float* mp = cp_means + ((size_t)k * BATCH + b) * 2;
            const float* cp = cp_cov   + ((size_t)k * BATCH + b) * 4;
            mx += wk * __ldg(mp + 0);
            my += wk * __ldg(mp + 1);
            ca += w2 * __ldg(cp + 0);
            cb += w2 * __ldg(cp + 1);
            cd += w2 * __ldg(cp + 3);
        }

        const float det  = ca * cd - cb * cb;
        const float rdet = 1.0f / det;
        const float NL2E = -0.72134752044448170f;     // -0.5 * log2(e)
        sco[0][t] = mx;
        sco[1][t] = my;
        sco[2][t] = NL2E * cd * rdet;                 // Af  (dx^2)
        sco[3][t] = -2.0f * NL2E * cb * rdet;         // Bf  (dx*dy)
        sco[4][t] = NL2E * ca * rdet;                 // Cf  (dy^2)
        sco[5][t] = -0.5f * __log2f(39.478417604357434f * det); // folded norm
    }
    __syncthreads();

    // ---- Main evaluation ----
    const int tq = tid & 15;     // t-quad: t = 4*tq .. 4*tq+3
    const int yg = tid >> 4;     // y-group 0..15; y = yg + 16*yi

    const float4 MX = ((const float4*)sco[0])[tq];
    const float4 MY = ((const float4*)sco[1])[tq];
    const float4 AF = ((const float4*)sco[2])[tq];
    const float4 BF = ((const float4*)sco[3])[tq];
    const float4 CF = ((const float4*)sco[4])[tq];
    const float4 LS = ((const float4*)sco[5])[tq];

    const float mx[4] = {MX.x, MX.y, MX.z, MX.w};
    const float my[4] = {MY.x, MY.y, MY.z, MY.w};
    const float Af[4] = {AF.x, AF.y, AF.z, AF.w};
    const float Bf[4] = {BF.x, BF.y, BF.z, BF.w};
    const float Cf[4] = {CF.x, CF.y, CF.z, CF.w};
    const float ls[4] = {LS.x, LS.y, LS.z, LS.w};

    float ym[4];
    #pragma unroll
    for (int j = 0; j < 4; j++) ym[j] = (float)yg - my[j];

    float* ob = out + (((size_t)b * MAP_W + x0) * MAP_H) * T_SIZE + (tq << 2);

    #pragma unroll
    for (int xi = 0; xi < 4; xi++) {
        const float xf = (float)(x0 + xi);
        float A2[4], Bd[4];
        #pragma unroll
        for (int j = 0; j < 4; j++) {
            const float dx = xf - mx[j];
            A2[j] = fmaf(Af[j] * dx, dx, ls[j]);   // Af*dx^2 + log2-scale
            Bd[j] = Bf[j] * dx;
        }

        float dy0 = ym[0], dy1 = ym[1], dy2 = ym[2], dy3 = ym[3];
        float* orow = ob + (size_t)xi * MAP_H * T_SIZE + (size_t)yg * T_SIZE;

        #pragma unroll
        for (int yi = 0; yi < 4; yi++) {
            float4 v;
            v.x = ex2(fmaf(fmaf(Cf[0], dy0, Bd[0]), dy0, A2[0]));
            v.y = ex2(fmaf(fmaf(Cf[1], dy1, Bd[1]), dy1, A2[1]));
            v.z = ex2(fmaf(fmaf(Cf[2], dy2, Bd[2]), dy2, A2[2]));
            v.w = ex2(fmaf(fmaf(Cf[3], dy3, Bd[3]), dy3, A2[3]));
            __stcs((float4*)(orow + (size_t)yi * 16 * T_SIZE), v);
            dy0 += 16.0f; dy1 += 16.0f; dy2 += 16.0f; dy3 += 16.0f;
        }
    }
}

extern "C" void kernel_launch(void* const* d_in, const int* in_sizes, int n_in,
                              void* d_out, int out_size)
{
    const float* cp_means = (const float*)d_in[0];   // (8, 128, 2)
    const int*   num_cps  = (const int*)  d_in[1];   // (128,)
    const float* cp_cov   = (const float*)d_in[2];   // (8, 128, 2, 2)
    float* out = (float*)d_out;                      // (128, 64, 64, 64)

    dim3 grid(BATCH * (MAP_W / 4));
    dim3 block(256);
    probmap_kernel<<<grid, block>>>(cp_means, num_cps, cp_cov, out);
}

// round 6
// speedup vs baseline: 1.4917x; 1.0102x over previous
#include <cuda_runtime.h>
#include <cuda_bf16.h>

#define MAP_W   64
#define MAP_H   64
#define T_SIZE  64
#define NUM_CP  8
#define BATCH   128

// Binomial coefficients C(m, k)
__device__ const float BINOM[8][8] = {
    {1, 0, 0,  0,  0,  0,  0, 0},
    {1, 1, 0,  0,  0,  0,  0, 0},
    {1, 2, 1,  0,  0,  0,  0, 0},
    {1, 3, 3,  1,  0,  0,  0, 0},
    {1, 4, 6,  4,  1,  0,  0, 0},
    {1, 5, 10, 10, 5,  1,  0, 0},
    {1, 6, 15, 20, 15, 6,  1, 0},
    {1, 7, 21, 35, 35, 21, 7, 1},
};

__device__ __forceinline__ float ex2(float x) {
    float y;
    asm("ex2.approx.ftz.f32 %0, %1;" : "=f"(y) : "f"(x));
    return y;
}

// Block = (b, 4 x-columns). 256 threads = 16 t-quads x 16 y-groups.
// Each thread: 4 consecutive t (float4 store), 4 x, 4 y -> 64 outputs.
// Grid: 2048 independent blocks. Default-policy stores: lines surviving in L2
// across graph replays are overwritten in place, saving DRAM writeback traffic.
__global__ __launch_bounds__(256, 4)
void probmap_kernel(const float* __restrict__ cp_means,
                    const int*   __restrict__ num_cps,
                    const float* __restrict__ cp_cov,
                    float*       __restrict__ out)
{
    __shared__ float sco[6][64];   // per-t coeffs: mx, my, Af, Bf, Cf, lscale

    const int b   = blockIdx.x >> 4;
    const int x0  = (blockIdx.x & 15) << 2;
    const int tid = threadIdx.x;

    // ---- Cooperative per-t coefficient setup (one thread per t) ----
    if (tid < 64) {
        const int   t  = tid;
        const int   m  = num_cps[b] - 1;          // degree 2..7
        const float tt = (float)t * (1.0f / 63.0f);
        const float u  = 1.0f - tt;

        float up[NUM_CP];
        up[0] = 1.0f;
        #pragma unroll
        for (int j = 1; j < NUM_CP; j++) up[j] = up[j - 1] * u;

        float w[NUM_CP];
        float tk = 1.0f;
        #pragma unroll
        for (int k = 0; k < NUM_CP; k++) {
            w[k] = (k <= m) ? BINOM[m][k] * tk * up[m - k] : 0.0f;
            tk *= tt;
        }

        float mx = 0.f, my = 0.f, ca = 0.f, cb = 0.f, cd = 0.f;
        #pragma unroll
        for (int k = 0; k < NUM_CP; k++) {
            const float wk = w[k];
            const float w2 = wk * wk;
            const float* mp = cp_means + ((size_t)k * BATCH + b) * 2;
            const float* cp = cp_cov   + ((size_t)k * BATCH + b) * 4;
            mx += wk * __ldg(mp + 0);
            my += wk * __ldg(mp + 1);
            ca += w2 * __ldg(cp + 0);
            cb += w2 * __ldg(cp + 1);
            cd += w2 * __ldg(cp + 3);
        }

        const float det  = ca * cd - cb * cb;
        const float rdet = 1.0f / det;
        const float NL2E = -0.72134752044448170f;     // -0.5 * log2(e)
        sco[0][t] = mx;
        sco[1][t] = my;
        sco[2][t] = NL2E * cd * rdet;                 // Af  (dx^2)
        sco[3][t] = -2.0f * NL2E * cb * rdet;         // Bf  (dx*dy)
        sco[4][t] = NL2E * ca * rdet;                 // Cf  (dy^2)
        sco[5][t] = -0.5f * __log2f(39.478417604357434f * det); // folded norm
    }
    __syncthreads();

    // ---- Main evaluation ----
    const int tq = tid & 15;     // t-quad: t = 4*tq .. 4*tq+3
    const int yg = tid >> 4;     // y-group 0..15; y = yg + 16*yi

    const float4 MX = ((const float4*)sco[0])[tq];
    const float4 MY = ((const float4*)sco[1])[tq];
    const float4 AF = ((const float4*)sco[2])[tq];
    const float4 BF = ((const float4*)sco[3])[tq];
    const float4 CF = ((const float4*)sco[4])[tq];
    const float4 LS = ((const float4*)sco[5])[tq];

    const float mx[4] = {MX.x, MX.y, MX.z, MX.w};
    const float my[4] = {MY.x, MY.y, MY.z, MY.w};
    const float Af[4] = {AF.x, AF.y, AF.z, AF.w};
    const float Bf[4] = {BF.x, BF.y, BF.z, BF.w};
    const float Cf[4] = {CF.x, CF.y, CF.z, CF.w};
    const float ls[4] = {LS.x, LS.y, LS.z, LS.w};

    float ym[4];
    #pragma unroll
    for (int j = 0; j < 4; j++) ym[j] = (float)yg - my[j];

    float* ob = out + (((size_t)b * MAP_W + x0) * MAP_H) * T_SIZE + (tq << 2);

    #pragma unroll
    for (int xi = 0; xi < 4; xi++) {
        const float xf = (float)(x0 + xi);
        float A2[4], Bd[4];
        #pragma unroll
        for (int j = 0; j < 4; j++) {
            const float dx = xf - mx[j];
            A2[j] = fmaf(Af[j] * dx, dx, ls[j]);   // Af*dx^2 + log2-scale
            Bd[j] = Bf[j] * dx;
        }

        float dy0 = ym[0], dy1 = ym[1], dy2 = ym[2], dy3 = ym[3];
        float* orow = ob + (size_t)xi * MAP_H * T_SIZE + (size_t)yg * T_SIZE;

        #pragma unroll
        for (int yi = 0; yi < 4; yi++) {
            float4 v;
            v.x = ex2(fmaf(fmaf(Cf[0], dy0, Bd[0]), dy0, A2[0]));
            v.y = ex2(fmaf(fmaf(Cf[1], dy1, Bd[1]), dy1, A2[1]));
            v.z = ex2(fmaf(fmaf(Cf[2], dy2, Bd[2]), dy2, A2[2]));
            v.w = ex2(fmaf(fmaf(Cf[3], dy3, Bd[3]), dy3, A2[3]));
            *(float4*)(orow + (size_t)yi * 16 * T_SIZE) = v;   // default policy
            dy0 += 16.0f; dy1 += 16.0f; dy2 += 16.0f; dy3 += 16.0f;
        }
    }
}

extern "C" void kernel_launch(void* const* d_in, const int* in_sizes, int n_in,
                              void* d_out, int out_size)
{
    const float* cp_means = (const float*)d_in[0];   // (8, 128, 2)
    const int*   num_cps  = (const int*)  d_in[1];   // (128,)
    const float* cp_cov   = (const float*)d_in[2];   // (8, 128, 2, 2)
    float* out = (float*)d_out;                      // (128, 64, 64, 64)

    dim3 grid(BATCH * (MAP_W / 4));
    dim3 block(256);
    probmap_kernel<<<grid, block>>>(cp_means, num_cps, cp_cov, out);
}